// round 1
// baseline (speedup 1.0000x reference)
#include <cuda_runtime.h>
#include <cstddef>

// ---------------------------------------------------------------------------
// BlockCNN: periodic-pad(4) -> conv5^3 (3->16) -> conv3^3 (16->16) -> conv3^3 (16->3)
// x: [4,3,96,96,96] fp32, out: [4,3,96,96,96] fp32
// ---------------------------------------------------------------------------

#define BATCH 4
#define S0    96
#define HALO  4

// Intermediate activations in device-global scratch (no allocations allowed).
__device__ float g_h1[(size_t)BATCH * 16 * 100 * 100 * 100]; // 256 MB
__device__ float g_h2[(size_t)BATCH * 16 * 98 * 98 * 98];    // 241 MB

// ---------------------------------------------------------------------------
// Tiled direct 3D conv. Each thread computes OCB out-channels x XB x-positions.
// Input tile + weights staged in shared memory; inner loop keeps the x-row and
// the (ic,kz,ky) weight slice in registers -> FFMA:LDS ratio ~5.6:1.
// WRAP=true folds periodic padding into the gmem->smem tile load (conv1 only).
// ---------------------------------------------------------------------------

template <int IC, int OC, int K, int OCB, int TZ, int TY, int TXG, int XB, bool WRAP>
struct ConvCfg {
    static constexpr int TX  = TXG * XB;
    static constexpr int SZ  = TZ + K - 1;
    static constexpr int SY  = TY + K - 1;
    static constexpr int SXr = TX + K - 1;
    static constexpr int SX  = (SXr % 2 == 0) ? (SXr + 1) : SXr;   // odd stride: tame bank conflicts
    static constexpr int NT  = (OC / OCB) * TZ * TY * TXG;         // threads per block
    static constexpr int SMEM_FLOATS = IC * SZ * SY * SX + OC * IC * K * K * K + OC;
    static constexpr int SMEM_BYTES  = SMEM_FLOATS * 4;
};

template <int IC, int OC, int K, int OCB, int TZ, int TY, int TXG, int XB, bool WRAP>
__global__ void __launch_bounds__(((OC / OCB) * TZ * TY * TXG))
conv3d_kernel(const float* __restrict__ in, const float* __restrict__ Wt,
              const float* __restrict__ bias, float* __restrict__ out,
              int Sin, int Sout, int nbz)
{
    using C = ConvCfg<IC, OC, K, OCB, TZ, TY, TXG, XB, WRAP>;
    constexpr int K3 = K * K * K;

    extern __shared__ float sm[];
    float* sIn = sm;
    float* sW  = sm + IC * C::SZ * C::SY * C::SX;
    float* sB  = sW + OC * IC * K3;

    const int tid = threadIdx.x;
    const int bz  = blockIdx.z % nbz;
    const int b   = blockIdx.z / nbz;
    const int x0  = blockIdx.x * C::TX;
    const int y0  = blockIdx.y * TY;
    const int z0  = bz * TZ;

    // ---- cooperative gmem -> smem input tile load ----
    const size_t inBase = (size_t)b * IC * (size_t)Sin * Sin * Sin;
    for (int e = tid; e < IC * C::SZ * C::SY * C::SXr; e += C::NT) {
        int xx = e % C::SXr; int r = e / C::SXr;
        int yy = r % C::SY;  r /= C::SY;
        int zz = r % C::SZ;  int ic = r / C::SZ;
        const int gx = x0 + xx, gy = y0 + yy, gz = z0 + zz;
        float v;
        if (WRAP) {
            // virtual padded coordinate g maps to source (g - HALO) mod Sin
            const int wx = (gx + Sin - HALO) % Sin;
            const int wy = (gy + Sin - HALO) % Sin;
            const int wz = (gz + Sin - HALO) % Sin;
            v = in[inBase + (((size_t)ic * Sin + wz) * Sin + wy) * Sin + wx];
        } else {
            v = 0.f;
            if (gx < Sin && gy < Sin && gz < Sin)
                v = in[inBase + (((size_t)ic * Sin + gz) * Sin + gy) * Sin + gx];
        }
        sIn[((ic * C::SZ + zz) * C::SY + yy) * C::SX + xx] = v;
    }
    for (int e = tid; e < OC * IC * K3; e += C::NT) sW[e] = Wt[e];
    for (int e = tid; e < OC; e += C::NT) sB[e] = bias[e];
    __syncthreads();

    // ---- thread decode ----
    int t = tid;
    const int xg  = t % TXG; t /= TXG;
    const int ty  = t % TY;  t /= TY;
    const int tz  = t % TZ;  t /= TZ;
    const int oc0 = t * OCB;
    const int txb = xg * XB;

    float acc[OCB][XB];
#pragma unroll
    for (int o = 0; o < OCB; ++o)
#pragma unroll
        for (int j = 0; j < XB; ++j) acc[o][j] = 0.f;

#pragma unroll 1
    for (int ic = 0; ic < IC; ++ic) {
        const float* sI = sIn + ic * C::SZ * C::SY * C::SX;
#pragma unroll 1
        for (int kz = 0; kz < K; ++kz) {
            const float* sIz = sI + (tz + kz) * C::SY * C::SX + ty * C::SX + txb;
            const float* wpz = sW + (oc0 * IC + ic) * K3 + kz * K * K;
#pragma unroll
            for (int ky = 0; ky < K; ++ky) {
                const float* row = sIz + ky * C::SX;
                float inv[XB + K - 1];
#pragma unroll
                for (int i = 0; i < XB + K - 1; ++i) inv[i] = row[i];
                float w[OCB][K];
#pragma unroll
                for (int o = 0; o < OCB; ++o) {
                    const float* wp = wpz + o * IC * K3 + ky * K;
#pragma unroll
                    for (int kx = 0; kx < K; ++kx) w[o][kx] = wp[kx];
                }
#pragma unroll
                for (int kx = 0; kx < K; ++kx)
#pragma unroll
                    for (int o = 0; o < OCB; ++o)
#pragma unroll
                        for (int j = 0; j < XB; ++j)
                            acc[o][j] += w[o][kx] * inv[j + kx];
            }
        }
    }

    // ---- store ----
    const int gz = z0 + tz, gy = y0 + ty;
    if (gz < Sout && gy < Sout) {
#pragma unroll
        for (int o = 0; o < OCB; ++o) {
            const float bb = sB[oc0 + o];
            const size_t ob = ((((size_t)b * OC + oc0 + o) * Sout + gz) * Sout + gy) * (size_t)Sout;
#pragma unroll
            for (int j = 0; j < XB; ++j) {
                const int gx = x0 + txb + j;
                if (gx < Sout) out[ob + gx] = acc[o][j] + bb;
            }
        }
    }
}

// ---------------------------------------------------------------------------
// Layer configurations
// ---------------------------------------------------------------------------
// conv1: 3 -> 16, K=5, wrap-padded input (virtual 104^3), out 100^3
using Cfg1 = ConvCfg<3, 16, 5, 8, 4, 8, 2, 8, true>;
// conv2: 16 -> 16, K=3, in 100^3, out 98^3
using Cfg2 = ConvCfg<16, 16, 3, 8, 4, 8, 2, 8, false>;
// conv3: 16 -> 3, K=3, in 98^3, out 96^3
using Cfg3 = ConvCfg<16, 3, 3, 3, 4, 8, 2, 8, false>;

static inline int cdiv(int a, int b) { return (a + b - 1) / b; }

extern "C" void kernel_launch(void* const* d_in, const int* in_sizes, int n_in,
                              void* d_out, int out_size)
{
    const float* x  = (const float*)d_in[0];
    const float* W1 = (const float*)d_in[1];
    const float* b1 = (const float*)d_in[2];
    const float* W2 = (const float*)d_in[3];
    const float* b2 = (const float*)d_in[4];
    const float* W3 = (const float*)d_in[5];
    const float* b3 = (const float*)d_in[6];
    float* out = (float*)d_out;

    float *h1, *h2;
    cudaGetSymbolAddress((void**)&h1, g_h1);
    cudaGetSymbolAddress((void**)&h2, g_h2);

    // Opt in to >48KB dynamic smem (idempotent; persists across calls).
    cudaFuncSetAttribute(conv3d_kernel<3, 16, 5, 8, 4, 8, 2, 8, true>,
                         cudaFuncAttributeMaxDynamicSharedMemorySize, Cfg1::SMEM_BYTES);
    cudaFuncSetAttribute(conv3d_kernel<16, 16, 3, 8, 4, 8, 2, 8, false>,
                         cudaFuncAttributeMaxDynamicSharedMemorySize, Cfg2::SMEM_BYTES);
    cudaFuncSetAttribute(conv3d_kernel<16, 3, 3, 3, 4, 8, 2, 8, false>,
                         cudaFuncAttributeMaxDynamicSharedMemorySize, Cfg3::SMEM_BYTES);

    // ---- conv1: x (wrap) -> h1, out 100^3 ----
    {
        const int Sout = 100, Sin = 96;
        const int nbz = cdiv(Sout, 4);
        dim3 grid(cdiv(Sout, Cfg1::TX), cdiv(Sout, 8), nbz * BATCH);
        conv3d_kernel<3, 16, 5, 8, 4, 8, 2, 8, true>
            <<<grid, Cfg1::NT, Cfg1::SMEM_BYTES>>>(x, W1, b1, h1, Sin, Sout, nbz);
    }
    // ---- conv2: h1 -> h2, out 98^3 ----
    {
        const int Sout = 98, Sin = 100;
        const int nbz = cdiv(Sout, 4);
        dim3 grid(cdiv(Sout, Cfg2::TX), cdiv(Sout, 8), nbz * BATCH);
        conv3d_kernel<16, 16, 3, 8, 4, 8, 2, 8, false>
            <<<grid, Cfg2::NT, Cfg2::SMEM_BYTES>>>(h1, W2, b2, h2, Sin, Sout, nbz);
    }
    // ---- conv3: h2 -> out, out 96^3 ----
    {
        const int Sout = 96, Sin = 98;
        const int nbz = cdiv(Sout, 4);
        dim3 grid(cdiv(Sout, Cfg3::TX), cdiv(Sout, 8), nbz * BATCH);
        conv3d_kernel<16, 3, 3, 3, 4, 8, 2, 8, false>
            <<<grid, Cfg3::NT, Cfg3::SMEM_BYTES>>>(h2, W3, b3, out, Sin, Sout, nbz);
    }
}

// round 3
// speedup vs baseline: 1.3190x; 1.3190x over previous
#include <cuda_runtime.h>
#include <cstddef>

// ---------------------------------------------------------------------------
// BlockCNN: periodic-pad(4) -> conv5^3 (3->16) -> conv3^3 (16->16) -> conv3^3 (16->3)
// Round 3 (= round-2 retry after infra failure): packed fp32x2 FMA
// (fma.rn.f32x2) — 2 FMAs/instr on the fma pipe. Accumulators packed over
// output-channel pairs; weights pre-interleaved in smem with oc innermost so
// LDS.64 yields a ready-packed weight pair.
// ---------------------------------------------------------------------------

#define BATCH 4
#define HALO  4

__device__ float g_h1[(size_t)BATCH * 16 * 100 * 100 * 100]; // 256 MB
__device__ float g_h2[(size_t)BATCH * 16 * 98 * 98 * 98];    // 241 MB

__device__ __forceinline__ unsigned long long dup_f32(float v) {
    unsigned long long d;
    asm("mov.b64 %0, {%1, %1};" : "=l"(d) : "f"(v));
    return d;
}
__device__ __forceinline__ void fma2(unsigned long long& acc,
                                     unsigned long long w2,
                                     unsigned long long x2) {
    asm("fma.rn.f32x2 %0, %1, %2, %0;" : "+l"(acc) : "l"(w2), "l"(x2));
}
__device__ __forceinline__ void unpack2(unsigned long long p, float& lo, float& hi) {
    asm("mov.b64 {%0, %1}, %2;" : "=f"(lo), "=f"(hi) : "l"(p));
}

// OCP = padded oc count in smem (weights beyond OC are zeroed). OCB must be even.
template <int IC, int OC, int OCP, int K, int OCB, int TZ, int TY, int TXG, int XB, bool WRAP>
struct ConvCfg {
    static constexpr int TX  = TXG * XB;
    static constexpr int SZ  = TZ + K - 1;
    static constexpr int SY  = TY + K - 1;
    static constexpr int SXr = TX + K - 1;
    static constexpr int SX  = (SXr % 2 == 0) ? (SXr + 1) : SXr;   // odd stride vs bank conflicts
    static constexpr int NT  = (OCP / OCB) * TZ * TY * TXG;
    static constexpr int K3  = K * K * K;
    static constexpr int SMEM_FLOATS = IC * SZ * SY * SX + IC * K3 * OCP + OCP;
    static constexpr int SMEM_BYTES  = SMEM_FLOATS * 4;
};

template <int IC, int OC, int OCP, int K, int OCB, int TZ, int TY, int TXG, int XB, bool WRAP>
__global__ void __launch_bounds__(((OCP / OCB) * TZ * TY * TXG))
conv3d_kernel(const float* __restrict__ in, const float* __restrict__ Wt,
              const float* __restrict__ bias, float* __restrict__ out,
              int Sin, int Sout, int nbz)
{
    using C = ConvCfg<IC, OC, OCP, K, OCB, TZ, TY, TXG, XB, WRAP>;
    constexpr int K3 = C::K3;
    constexpr int NP = OCB / 2;          // packed oc pairs per thread

    extern __shared__ float sm[];
    float* sIn = sm;
    float* sW  = sm + IC * C::SZ * C::SY * C::SX;   // layout [ic][kz][ky][kx][OCP]
    float* sB  = sW + IC * K3 * OCP;

    const int tid = threadIdx.x;
    const int bz  = blockIdx.z % nbz;
    const int b   = blockIdx.z / nbz;
    const int x0  = blockIdx.x * C::TX;
    const int y0  = blockIdx.y * TY;
    const int z0  = bz * TZ;

    // ---- cooperative gmem -> smem input tile ----
    const size_t inBase = (size_t)b * IC * (size_t)Sin * Sin * Sin;
    for (int e = tid; e < IC * C::SZ * C::SY * C::SXr; e += C::NT) {
        int xx = e % C::SXr; int r = e / C::SXr;
        int yy = r % C::SY;  r /= C::SY;
        int zz = r % C::SZ;  int ic = r / C::SZ;
        const int gx = x0 + xx, gy = y0 + yy, gz = z0 + zz;
        float v;
        if (WRAP) {
            const int wx = (gx + Sin - HALO) % Sin;
            const int wy = (gy + Sin - HALO) % Sin;
            const int wz = (gz + Sin - HALO) % Sin;
            v = in[inBase + (((size_t)ic * Sin + wz) * Sin + wy) * Sin + wx];
        } else {
            v = 0.f;
            if (gx < Sin && gy < Sin && gz < Sin)
                v = in[inBase + (((size_t)ic * Sin + gz) * Sin + gy) * Sin + gx];
        }
        sIn[((ic * C::SZ + zz) * C::SY + yy) * C::SX + xx] = v;
    }
    // ---- weights: transpose to oc-innermost, zero-pad oc >= OC ----
    for (int e = tid; e < IC * K3 * OCP; e += C::NT) {
        const int oc = e % OCP; int r = e / OCP;
        const int kx = r % K;  r /= K;
        const int ky = r % K;  r /= K;
        const int kz = r % K;  const int ic = r / K;
        float v = 0.f;
        if (oc < OC)
            v = Wt[((((size_t)oc * IC + ic) * K + kz) * K + ky) * K + kx];
        sW[e] = v;
    }
    for (int e = tid; e < OCP; e += C::NT) sB[e] = (e < OC) ? bias[e] : 0.f;
    __syncthreads();

    // ---- thread decode ----
    int t = tid;
    const int xg  = t % TXG; t /= TXG;
    const int ty  = t % TY;  t /= TY;
    const int tz  = t % TZ;  t /= TZ;
    const int oc0 = t * OCB;            // even
    const int txb = xg * XB;

    unsigned long long acc[NP][XB];
#pragma unroll
    for (int p = 0; p < NP; ++p)
#pragma unroll
        for (int j = 0; j < XB; ++j) acc[p][j] = 0ull;

#pragma unroll 1
    for (int ic = 0; ic < IC; ++ic) {
        const float* sI = sIn + ic * C::SZ * C::SY * C::SX;
#pragma unroll 1
        for (int kz = 0; kz < K; ++kz) {
            const float* sIz = sI + (tz + kz) * C::SY * C::SX + ty * C::SX + txb;
            const float* wkz = sW + ((ic * K + kz) * K) * K * OCP;
#pragma unroll
            for (int ky = 0; ky < K; ++ky) {
                const float* row = sIz + ky * C::SX;
                // front-batch the input row (broadcast-packed) ...
                unsigned long long x2[XB + K - 1];
#pragma unroll
                for (int i = 0; i < XB + K - 1; ++i) x2[i] = dup_f32(row[i]);
                // ... and the packed weight pairs for this ky row
                const float* wky = wkz + ky * K * OCP;
                unsigned long long w2[K][NP];
#pragma unroll
                for (int kx = 0; kx < K; ++kx)
#pragma unroll
                    for (int p = 0; p < NP; ++p)
                        w2[kx][p] = *reinterpret_cast<const unsigned long long*>(
                            wky + kx * OCP + oc0 + 2 * p);
#pragma unroll
                for (int kx = 0; kx < K; ++kx)
#pragma unroll
                    for (int p = 0; p < NP; ++p)
#pragma unroll
                        for (int j = 0; j < XB; ++j)
                            fma2(acc[p][j], w2[kx][p], x2[j + kx]);
            }
        }
    }

    // ---- store ----
    const int gz = z0 + tz, gy = y0 + ty;
    if (gz < Sout && gy < Sout) {
#pragma unroll
        for (int p = 0; p < NP; ++p) {
            const int ocA = oc0 + 2 * p, ocB = ocA + 1;
            const float bA = sB[ocA], bB = sB[ocB];
            const size_t obA = ((((size_t)b * OC + ocA) * Sout + gz) * Sout + gy) * (size_t)Sout;
            const size_t obB = ((((size_t)b * OC + ocB) * Sout + gz) * Sout + gy) * (size_t)Sout;
#pragma unroll
            for (int j = 0; j < XB; ++j) {
                const int gx = x0 + txb + j;
                if (gx < Sout) {
                    float lo, hi;
                    unpack2(acc[p][j], lo, hi);
                    if (ocA < OC) out[obA + gx] = lo + bA;
                    if (ocB < OC) out[obB + gx] = hi + bB;
                }
            }
        }
    }
}

// conv1: 3 -> 16, K=5, wrap (virtual 104^3), out 100^3.  NT=256, smem ~48KB
using Cfg1 = ConvCfg<3, 16, 16, 5, 4, 4, 8, 2, 8, true>;
// conv2: 16 -> 16, K=3, in 100^3, out 98^3.              NT=256, smem ~101KB
using Cfg2 = ConvCfg<16, 16, 16, 3, 4, 4, 8, 2, 8, false>;
// conv3: 16 -> 3 (padded to 4), K=3, in 98^3, out 96^3.  NT=128, smem ~80KB
using Cfg3 = ConvCfg<16, 3, 4, 3, 2, 4, 8, 2, 8, false>;

static inline int cdiv(int a, int b) { return (a + b - 1) / b; }

extern "C" void kernel_launch(void* const* d_in, const int* in_sizes, int n_in,
                              void* d_out, int out_size)
{
    const float* x  = (const float*)d_in[0];
    const float* W1 = (const float*)d_in[1];
    const float* b1 = (const float*)d_in[2];
    const float* W2 = (const float*)d_in[3];
    const float* b2 = (const float*)d_in[4];
    const float* W3 = (const float*)d_in[5];
    const float* b3 = (const float*)d_in[6];
    float* out = (float*)d_out;

    float *h1, *h2;
    cudaGetSymbolAddress((void**)&h1, g_h1);
    cudaGetSymbolAddress((void**)&h2, g_h2);

    cudaFuncSetAttribute(conv3d_kernel<3, 16, 16, 5, 4, 4, 8, 2, 8, true>,
                         cudaFuncAttributeMaxDynamicSharedMemorySize, Cfg1::SMEM_BYTES);
    cudaFuncSetAttribute(conv3d_kernel<16, 16, 16, 3, 4, 4, 8, 2, 8, false>,
                         cudaFuncAttributeMaxDynamicSharedMemorySize, Cfg2::SMEM_BYTES);
    cudaFuncSetAttribute(conv3d_kernel<16, 3, 4, 3, 2, 4, 8, 2, 8, false>,
                         cudaFuncAttributeMaxDynamicSharedMemorySize, Cfg3::SMEM_BYTES);

    {   // conv1
        const int Sout = 100, Sin = 96;
        const int nbz = cdiv(Sout, 4);
        dim3 grid(cdiv(Sout, Cfg1::TX), cdiv(Sout, 8), nbz * BATCH);
        conv3d_kernel<3, 16, 16, 5, 4, 4, 8, 2, 8, true>
            <<<grid, Cfg1::NT, Cfg1::SMEM_BYTES>>>(x, W1, b1, h1, Sin, Sout, nbz);
    }
    {   // conv2
        const int Sout = 98, Sin = 100;
        const int nbz = cdiv(Sout, 4);
        dim3 grid(cdiv(Sout, Cfg2::TX), cdiv(Sout, 8), nbz * BATCH);
        conv3d_kernel<16, 16, 16, 3, 4, 4, 8, 2, 8, false>
            <<<grid, Cfg2::NT, Cfg2::SMEM_BYTES>>>(h1, W2, b2, h2, Sin, Sout, nbz);
    }
    {   // conv3
        const int Sout = 96, Sin = 98;
        const int nbz = cdiv(Sout, 4);
        dim3 grid(cdiv(Sout, Cfg3::TX), cdiv(Sout, 8), nbz * BATCH);
        conv3d_kernel<16, 3, 4, 3, 2, 4, 8, 2, 8, false>
            <<<grid, Cfg3::NT, Cfg3::SMEM_BYTES>>>(h2, W3, b3, out, Sin, Sout, nbz);
    }
}